// round 14
// baseline (speedup 1.0000x reference)
#include <cuda_runtime.h>
#include <cuda_bf16.h>
#include <math.h>
#include <stdint.h>

// ---------------------------------------------------------------------------
// BSPLoss: out = lam1 + 0.5*(lam2+lam3), lam_i = top eigenvalue of F_i^T F_i.
// Pipeline: F -> bf16 ; Gram via cp.async bf16 GEMM (4-way K-split, bf16
// partials) ; tiny add kernel sums partials -> bf16 G ; 9 Frobenius-
// normalized squarings via the proven cp.async bf16 GEMM.
// log2(lam) = sum 2^-k log2(c_k).  All GEMMs mma.sync bf16, fp32 accum.
// ---------------------------------------------------------------------------

#define DIM    1024
#define NROWS  8192
#define M_SQ   9
#define NTILE  36
#define KSPLIT 4

#define KCS     32
#define SREGB   (KCS * 256)          // 8 KB per operand region
#define SSTAGEB (2 * SREGB)          // 16 KB per stage
#define NSTG    4
#define CSMEMB  (NSTG * SSTAGEB)     // 64 KB

__device__ __align__(16) __nv_bfloat16  g_part16[KSPLIT][3][DIM * DIM];
__device__ __align__(16) __nv_bfloat16  g_hbuf[2][3][DIM * DIM];
__device__ __align__(16) __nv_bfloat16  g_fbuf[3][NROWS * DIM];
__device__ double g_frob[3];
__device__ float  g_inv[3];
__device__ double g_logacc[3];
__device__ int    g_ctr[3];

__global__ void init_kernel() {
    int i = threadIdx.x;
    if (i < 3) { g_frob[i] = 0.0; g_inv[i] = 1.0f; g_logacc[i] = 0.0; g_ctr[i] = 0; }
}

__device__ __forceinline__ uint32_t smem_u32(const void* p) {
    uint32_t a;
    asm("{ .reg .u64 t; cvta.to.shared.u64 t, %1; cvt.u32.u64 %0, t; }"
        : "=r"(a) : "l"(p));
    return a;
}

__device__ __forceinline__ void ldsm4t(uint32_t* r, uint32_t addr) {
    asm volatile("ldmatrix.sync.aligned.m8n8.x4.trans.shared.b16 {%0,%1,%2,%3}, [%4];"
                 : "=r"(r[0]), "=r"(r[1]), "=r"(r[2]), "=r"(r[3]) : "r"(addr));
}

__device__ __forceinline__ void mma16816(float* c, const uint32_t* a,
                                         uint32_t b0, uint32_t b1) {
    asm volatile("mma.sync.aligned.m16n8k16.row.col.f32.bf16.bf16.f32 "
                 "{%0,%1,%2,%3}, {%4,%5,%6,%7}, {%8,%9}, {%0,%1,%2,%3};"
                 : "+f"(c[0]), "+f"(c[1]), "+f"(c[2]), "+f"(c[3])
                 : "r"(a[0]), "r"(a[1]), "r"(a[2]), "r"(a[3]), "r"(b0), "r"(b1));
}

__device__ __forceinline__ uint32_t swz256(uint32_t base, int row, int chunk) {
    return base + row * 256 + ((chunk ^ (row & 7)) << 4);
}

__device__ __forceinline__ void cvt_h(float4 v, uint2& hi) {
    __nv_bfloat162 h0 = __floats2bfloat162_rn(v.x, v.y);
    __nv_bfloat162 h1 = __floats2bfloat162_rn(v.z, v.w);
    hi.x = *(uint32_t*)&h0; hi.y = *(uint32_t*)&h1;
}

#define CP_ASYNC16(dst, src) \
    asm volatile("cp.async.ca.shared.global [%0], [%1], 16;" \
                 :: "r"(dst), "l"(src) : "memory")
#define CP_COMMIT() asm volatile("cp.async.commit_group;" ::: "memory")
#define CP_WAIT2()  asm volatile("cp.async.wait_group 2;" ::: "memory")

// ============ fp32 -> bf16 conversion pre-pass ============
__global__ void __launch_bounds__(256)
cvt_kernel(const float* __restrict__ a0, const float* __restrict__ a1,
           const float* __restrict__ a2)
{
    const int z = blockIdx.y;
    const float* A = (z == 0) ? a0 : ((z == 1) ? a1 : a2);
    __nv_bfloat16* D = g_fbuf[z];
    const int n = NROWS * DIM / 4;
    for (int i = blockIdx.x * blockDim.x + threadIdx.x; i < n;
         i += gridDim.x * blockDim.x) {
        float4 v = *(const float4*)(A + (size_t)i * 4);
        uint2 h;
        cvt_h(v, h);
        *(uint2*)(D + (size_t)i * 4) = h;
    }
}

// ---- fragment helpers (warp tile 64x32) ----
__device__ __forceinline__ void load_frags(uint32_t u, int kk, int wm, int wn,
                                           int g, int tr,
                                           uint32_t ah[4][4], uint32_t bh[2][4]) {
    const int rowB = kk + ((g & 1) ? 8 : 0) + tr;
#pragma unroll
    for (int nb = 0; nb < 2; nb++)
        ldsm4t(bh[nb], swz256(u + SREGB, rowB, (wn >> 3) + nb * 2 + (g >> 1)));
    const int rowA = kk + ((g & 2) ? 8 : 0) + tr;
#pragma unroll
    for (int mi = 0; mi < 4; mi++)
        ldsm4t(ah[mi], swz256(u, rowA, (wm >> 3) + mi * 2 + (g & 1)));
}

__device__ __forceinline__ void mma_step(float acc[4][4][4],
                                         uint32_t ah[4][4], uint32_t bh[2][4]) {
#pragma unroll
    for (int mi = 0; mi < 4; mi++)
#pragma unroll
        for (int nj = 0; nj < 4; nj++)
            mma16816(acc[mi][nj], ah[mi],
                     bh[nj >> 1][(nj & 1) * 2], bh[nj >> 1][(nj & 1) * 2 + 1]);
}

// ============ Gram kernel: cp.async bf16, tile 128x128, K-split grid ========
__global__ void __launch_bounds__(256, 1)
gram_cp_kernel()
{
    extern __shared__ __align__(16) char dynsmem[];

    const int z  = blockIdx.z;
    const int ky = blockIdx.y;
    const __nv_bfloat16* Ab = g_fbuf[z];
    __nv_bfloat16* C = g_part16[ky][z];

    int t = blockIdx.x, bi = 0;
    while (t >= 8 - bi) { t -= 8 - bi; bi++; }
    const int bj = bi + t;
    const int i0 = bi * 128, j0 = bj * 128;

    const int tid = threadIdx.x;
    const int w = tid >> 5, l = tid & 31;
    const int wm = (w >> 2) * 64;
    const int wn = (w & 3) * 32;
    const int tr = l & 7, g = l >> 3;
    const int row = tid >> 3;
    const int cb  = (tid & 7) * 2;

    const uint32_t sb = smem_u32(dynsmem);

    float acc[4][4][4];
#pragma unroll
    for (int mi = 0; mi < 4; mi++)
#pragma unroll
        for (int nj = 0; nj < 4; nj++)
#pragma unroll
            for (int q = 0; q < 4; q++) acc[mi][nj][q] = 0.0f;

    const __nv_bfloat16* baseI = Ab + i0;
    const __nv_bfloat16* baseJ = Ab + j0;
    const int kbase = ky * (NROWS / KSPLIT);

    const int S = (NROWS / KSPLIT) / KCS;   // 64 stages

    auto issue_stage = [&](int s) {
        const uint32_t bufb = sb + (uint32_t)(s & (NSTG - 1)) * SSTAGEB;
        const size_t krow = (size_t)(kbase + s * KCS + row) * DIM;
#pragma unroll
        for (int cc = 0; cc < 2; cc++) {
            const int ch = cb + cc;
            const uint32_t off = (uint32_t)(row * 256) + ((ch ^ (row & 7)) << 4);
            CP_ASYNC16(bufb + off,         baseI + krow + ch * 8);
            CP_ASYNC16(bufb + SREGB + off, baseJ + krow + ch * 8);
        }
    };

    issue_stage(0); CP_COMMIT();
    issue_stage(1); CP_COMMIT();
    issue_stage(2); CP_COMMIT();

    for (int s = 0; s < S; s++) {
        CP_WAIT2();
        __syncthreads();
        if (s + 3 < S) issue_stage(s + 3);
        CP_COMMIT();
        const uint32_t u = sb + (uint32_t)(s & (NSTG - 1)) * SSTAGEB;
        uint32_t ah[2][4][4], bh[2][2][4];
        load_frags(u, 0, wm, wn, g, tr, ah[0], bh[0]);
#pragma unroll
        for (int kk = 0; kk < KCS; kk += 16) {
            const int cu = (kk >> 4) & 1;
            if (kk + 16 < KCS)
                load_frags(u, kk + 16, wm, wn, g, tr, ah[cu ^ 1], bh[cu ^ 1]);
            mma_step(acc, ah[cu], bh[cu]);
        }
    }

    // epilogue: bf16 partial store + mirror
    const int r  = l >> 2;
    const int c2 = 2 * (l & 3);
#pragma unroll
    for (int mi = 0; mi < 4; mi++) {
#pragma unroll
        for (int nj = 0; nj < 4; nj++) {
            float* a = acc[mi][nj];
            const int gr = i0 + wm + mi * 16 + r;
            const int gc = j0 + wn + nj * 8 + c2;
            __nv_bfloat162 h01 = __floats2bfloat162_rn(a[0], a[1]);
            __nv_bfloat162 h23 = __floats2bfloat162_rn(a[2], a[3]);
            *reinterpret_cast<__nv_bfloat162*>(&C[(size_t)gr * DIM + gc])       = h01;
            *reinterpret_cast<__nv_bfloat162*>(&C[(size_t)(gr + 8) * DIM + gc]) = h23;
            if (bi != bj) {
                C[(size_t)gc * DIM + gr]           = h01.x;
                C[(size_t)(gc + 1) * DIM + gr]     = h01.y;
                C[(size_t)gc * DIM + gr + 8]       = h23.x;
                C[(size_t)(gc + 1) * DIM + gr + 8] = h23.y;
            }
        }
    }
}

// ============ sum 4 bf16 partial planes -> bf16 G ============
__global__ void __launch_bounds__(256)
add16_kernel()
{
    const int z = blockIdx.y;
    const uint2* p0 = reinterpret_cast<const uint2*>(g_part16[0][z]);
    const uint2* p1 = reinterpret_cast<const uint2*>(g_part16[1][z]);
    const uint2* p2 = reinterpret_cast<const uint2*>(g_part16[2][z]);
    const uint2* p3 = reinterpret_cast<const uint2*>(g_part16[3][z]);
    uint2* d = reinterpret_cast<uint2*>(g_hbuf[0][z]);
    const int n = DIM * DIM / 4;
    for (int i = blockIdx.x * blockDim.x + threadIdx.x; i < n;
         i += gridDim.x * blockDim.x) {
        uint2 a = p0[i], b = p1[i], c = p2[i], e = p3[i];
        __nv_bfloat162 a0 = *(__nv_bfloat162*)&a.x, a1 = *(__nv_bfloat162*)&a.y;
        __nv_bfloat162 b0 = *(__nv_bfloat162*)&b.x, b1 = *(__nv_bfloat162*)&b.y;
        __nv_bfloat162 c0 = *(__nv_bfloat162*)&c.x, c1 = *(__nv_bfloat162*)&c.y;
        __nv_bfloat162 e0 = *(__nv_bfloat162*)&e.x, e1 = *(__nv_bfloat162*)&e.y;
        float2 fa0 = __bfloat1622float2(a0), fa1 = __bfloat1622float2(a1);
        float2 fb0 = __bfloat1622float2(b0), fb1 = __bfloat1622float2(b1);
        float2 fc0 = __bfloat1622float2(c0), fc1 = __bfloat1622float2(c1);
        float2 fe0 = __bfloat1622float2(e0), fe1 = __bfloat1622float2(e1);
        float2 s0, s1;
        s0.x = (fa0.x + fb0.x) + (fc0.x + fe0.x);
        s0.y = (fa0.y + fb0.y) + (fc0.y + fe0.y);
        s1.x = (fa1.x + fb1.x) + (fc1.x + fe1.x);
        s1.y = (fa1.y + fb1.y) + (fc1.y + fe1.y);
        uint2 o;
        __nv_bfloat162 h0 = __floats2bfloat162_rn(s0.x, s0.y);
        __nv_bfloat162 h1 = __floats2bfloat162_rn(s1.x, s1.y);
        o.x = *(uint32_t*)&h0; o.y = *(uint32_t*)&h1;
        d[i] = o;
    }
}

// ---- shared epilogue for squaring kernel ----
__device__ __forceinline__ void sq_epilogue(float acc[4][4][4], int bi, int bj,
                                            int i0, int j0, int wm, int wn,
                                            int tid, int w, int l, float s2,
                                            int do_write, double wfin,
                                            __nv_bfloat16* Cb, int z,
                                            float* sh_wsum)
{
    const float w2 = (bi == bj) ? 1.0f : 2.0f;
    float fr = 0.0f;
    const int r  = l >> 2;
    const int c2 = 2 * (l & 3);
#pragma unroll
    for (int mi = 0; mi < 4; mi++) {
#pragma unroll
        for (int nj = 0; nj < 4; nj++) {
            float* a = acc[mi][nj];
#pragma unroll
            for (int q = 0; q < 4; q++) {
                a[q] *= s2;
                fr = fmaf(w2 * a[q], a[q], fr);
            }
            if (do_write) {
                const int gr = i0 + wm + mi * 16 + r;
                const int gc = j0 + wn + nj * 8 + c2;
                __nv_bfloat162 h01 = __floats2bfloat162_rn(a[0], a[1]);
                __nv_bfloat162 h23 = __floats2bfloat162_rn(a[2], a[3]);
                *reinterpret_cast<__nv_bfloat162*>(&Cb[(size_t)gr * DIM + gc]) = h01;
                *reinterpret_cast<__nv_bfloat162*>(&Cb[(size_t)(gr + 8) * DIM + gc]) = h23;
                if (bi != bj) {
                    Cb[(size_t)gc * DIM + gr]           = h01.x;
                    Cb[(size_t)(gc + 1) * DIM + gr]     = h01.y;
                    Cb[(size_t)gc * DIM + gr + 8]       = h23.x;
                    Cb[(size_t)(gc + 1) * DIM + gr + 8] = h23.y;
                }
            }
        }
    }
#pragma unroll
    for (int o = 16; o > 0; o >>= 1)
        fr += __shfl_xor_sync(0xffffffffu, fr, o);
    if (l == 0) sh_wsum[w] = fr;
    __syncthreads();
    if (tid == 0) {
        double tot = 0.0;
        for (int i = 0; i < 8; i++) tot += (double)sh_wsum[i];
        atomicAdd(&g_frob[z], tot);
        __threadfence();
        int tk = atomicAdd(&g_ctr[z], 1);
        if (tk == NTILE - 1) {
            g_ctr[z] = 0;
            __threadfence();
            double c = sqrt(g_frob[z]);
            g_inv[z] = (float)(1.0 / c);
            g_logacc[z] += log2(c) * wfin;
            g_frob[z] = 0.0;
        }
    }
}

// ===== squaring: 4-stage cp.async pipeline, bf16 chain (proven) =============
__global__ void __launch_bounds__(256, 1)
sq_cp_kernel(int src_sel, int dst_sel, int do_write, double wfin)
{
    extern __shared__ __align__(16) char dynsmem[];
    __shared__ float sh_wsum[8];

    const int z = blockIdx.z;
    const __nv_bfloat16* Ab = g_hbuf[src_sel][z];
    __nv_bfloat16* Cb = g_hbuf[dst_sel][z];

    int t = blockIdx.x, bi = 0;
    while (t >= 8 - bi) { t -= 8 - bi; bi++; }
    const int bj = bi + t;
    const int i0 = bi * 128, j0 = bj * 128;

    const int tid = threadIdx.x;
    const int w = tid >> 5, l = tid & 31;
    const int wm = (w >> 2) * 64;
    const int wn = (w & 3) * 32;
    const int tr = l & 7, g = l >> 3;
    const int row = tid >> 3;
    const int cb  = (tid & 7) * 2;

    const float sv = g_inv[z];
    const float s2 = sv * sv;

    const uint32_t sb = smem_u32(dynsmem);

    float acc[4][4][4];
#pragma unroll
    for (int mi = 0; mi < 4; mi++)
#pragma unroll
        for (int nj = 0; nj < 4; nj++)
#pragma unroll
            for (int q = 0; q < 4; q++) acc[mi][nj][q] = 0.0f;

    const __nv_bfloat16* baseI = Ab + i0;
    const __nv_bfloat16* baseJ = Ab + j0;

    const int S = DIM / KCS;

    auto issue_stage = [&](int s) {
        const uint32_t bufb = sb + (uint32_t)(s & (NSTG - 1)) * SSTAGEB;
        const size_t krow = (size_t)(s * KCS + row) * DIM;
#pragma unroll
        for (int cc = 0; cc < 2; cc++) {
            const int ch = cb + cc;
            const uint32_t off = (uint32_t)(row * 256) + ((ch ^ (row & 7)) << 4);
            CP_ASYNC16(bufb + off,         baseI + krow + ch * 8);
            CP_ASYNC16(bufb + SREGB + off, baseJ + krow + ch * 8);
        }
    };

    issue_stage(0); CP_COMMIT();
    issue_stage(1); CP_COMMIT();
    issue_stage(2); CP_COMMIT();

    for (int s = 0; s < S; s++) {
        CP_WAIT2();
        __syncthreads();
        if (s + 3 < S) issue_stage(s + 3);
        CP_COMMIT();
        const uint32_t u = sb + (uint32_t)(s & (NSTG - 1)) * SSTAGEB;
        uint32_t ah[2][4][4], bh[2][2][4];
        load_frags(u, 0, wm, wn, g, tr, ah[0], bh[0]);
#pragma unroll
        for (int kk = 0; kk < KCS; kk += 16) {
            const int cu = (kk >> 4) & 1;
            if (kk + 16 < KCS)
                load_frags(u, kk + 16, wm, wn, g, tr, ah[cu ^ 1], bh[cu ^ 1]);
            mma_step(acc, ah[cu], bh[cu]);
        }
    }
    __syncthreads();

    sq_epilogue(acc, bi, bj, i0, j0, wm, wn, tid, w, l, s2, do_write, wfin,
                Cb, z, sh_wsum);
}

__global__ void out_kernel(float* __restrict__ out) {
    double l0 = exp2(g_logacc[0]);
    double l1 = exp2(g_logacc[1]);
    double l2 = exp2(g_logacc[2]);
    out[0] = (float)(l0 + 0.5 * (l1 + l2));
}

extern "C" void kernel_launch(void* const* d_in, const int* in_sizes, int n_in,
                              void* d_out, int out_size)
{
    const float* f1 = (const float*)d_in[0];
    const float* f2 = (const float*)d_in[1];
    const float* f3 = (const float*)d_in[2];
    (void)in_sizes; (void)n_in; (void)out_size;

    static int configured = 0;
    if (!configured) {
        cudaFuncSetAttribute(gram_cp_kernel,
                             cudaFuncAttributeMaxDynamicSharedMemorySize, CSMEMB);
        cudaFuncSetAttribute(sq_cp_kernel,
                             cudaFuncAttributeMaxDynamicSharedMemorySize, CSMEMB);
        configured = 1;
    }

    init_kernel<<<1, 4>>>();

    // F -> bf16
    cvt_kernel<<<dim3(192, 3), 256>>>(f1, f2, f3);

    // Gram: 4-way K-split into bf16 partial planes, cp.async bf16 GEMM
    gram_cp_kernel<<<dim3(NTILE, KSPLIT, 3), 256, CSMEMB>>>();

    // sum partials -> bf16 G in hbuf[0]
    add16_kernel<<<dim3(108, 3), 256>>>();

    // 9 squarings, uniform cp.async kernel (k=1 has g_inv=1)
    int cur = 0;
    for (int k = 1; k <= M_SQ; k++) {
        int dst = 1 - cur;
        int dow = (k < M_SQ) ? 1 : 0;
        sq_cp_kernel<<<dim3(NTILE, 1, 3), 256, CSMEMB>>>(
            cur, dst, dow, exp2(-(double)k));
        cur = dst;
    }
    out_kernel<<<1, 1>>>((float*)d_out);
}

// round 16
// speedup vs baseline: 1.5880x; 1.5880x over previous
#include <cuda_runtime.h>
#include <cuda_bf16.h>
#include <math.h>
#include <stdint.h>

// ---------------------------------------------------------------------------
// BSPLoss: out = lam1 + 0.5*(lam2+lam3), lam_i = top eigenvalue of F_i^T F_i.
// Pipeline: F -> bf16 ; Gram via cp.async bf16 GEMM (4-way K-split, fp32
// partials, R13-proven) ; add32 sums partials -> bf16 G ; 9 Frobenius-
// normalized squarings via cp.async bf16 GEMM (KCS=64, 16 stages).
// log2(lam) = sum 2^-k log2(c_k).  All GEMMs mma.sync bf16, fp32 accum.
// ---------------------------------------------------------------------------

#define DIM    1024
#define NROWS  8192
#define M_SQ   9
#define NTILE  36
#define KSPLIT 4
#define PSTR   ((size_t)3 * DIM * DIM)

// Gram kernel constants (R13-proven: KC=32, 4-stage, 64 KB)
#define GKC     32
#define GREGB   (GKC * 256)          // 8 KB
#define GSTAGEB (2 * GREGB)          // 16 KB
#define GNSTG   4
#define GSMEMB  (GNSTG * GSTAGEB)    // 64 KB

// Squaring kernel constants (KC=64, 4-stage, 128 KB)
#define QKC     64
#define QREGB   (QKC * 256)          // 16 KB
#define QSTAGEB (2 * QREGB)          // 32 KB
#define QNSTG   4
#define QSMEMB  (QNSTG * QSTAGEB)    // 128 KB

__device__ __align__(16) float          g_part[KSPLIT][3][DIM * DIM];
__device__ __align__(16) __nv_bfloat16  g_hbuf[2][3][DIM * DIM];
__device__ __align__(16) __nv_bfloat16  g_fbuf[3][NROWS * DIM];
__device__ double g_frob[3];
__device__ float  g_inv[3];
__device__ double g_logacc[3];
__device__ int    g_ctr[3];

__global__ void init_kernel() {
    int i = threadIdx.x;
    if (i < 3) { g_frob[i] = 0.0; g_inv[i] = 1.0f; g_logacc[i] = 0.0; g_ctr[i] = 0; }
}

__device__ __forceinline__ uint32_t smem_u32(const void* p) {
    uint32_t a;
    asm("{ .reg .u64 t; cvta.to.shared.u64 t, %1; cvt.u32.u64 %0, t; }"
        : "=r"(a) : "l"(p));
    return a;
}

__device__ __forceinline__ void ldsm4t(uint32_t* r, uint32_t addr) {
    asm volatile("ldmatrix.sync.aligned.m8n8.x4.trans.shared.b16 {%0,%1,%2,%3}, [%4];"
                 : "=r"(r[0]), "=r"(r[1]), "=r"(r[2]), "=r"(r[3]) : "r"(addr));
}

__device__ __forceinline__ void mma16816(float* c, const uint32_t* a,
                                         uint32_t b0, uint32_t b1) {
    asm volatile("mma.sync.aligned.m16n8k16.row.col.f32.bf16.bf16.f32 "
                 "{%0,%1,%2,%3}, {%4,%5,%6,%7}, {%8,%9}, {%0,%1,%2,%3};"
                 : "+f"(c[0]), "+f"(c[1]), "+f"(c[2]), "+f"(c[3])
                 : "r"(a[0]), "r"(a[1]), "r"(a[2]), "r"(a[3]), "r"(b0), "r"(b1));
}

__device__ __forceinline__ uint32_t swz256(uint32_t base, int row, int chunk) {
    return base + row * 256 + ((chunk ^ (row & 7)) << 4);
}

__device__ __forceinline__ void cvt_h(float4 v, uint2& hi) {
    __nv_bfloat162 h0 = __floats2bfloat162_rn(v.x, v.y);
    __nv_bfloat162 h1 = __floats2bfloat162_rn(v.z, v.w);
    hi.x = *(uint32_t*)&h0; hi.y = *(uint32_t*)&h1;
}

#define CP_ASYNC16(dst, src) \
    asm volatile("cp.async.ca.shared.global [%0], [%1], 16;" \
                 :: "r"(dst), "l"(src) : "memory")
#define CP_COMMIT() asm volatile("cp.async.commit_group;" ::: "memory")
#define CP_WAIT2()  asm volatile("cp.async.wait_group 2;" ::: "memory")

// ============ fp32 -> bf16 conversion pre-pass ============
__global__ void __launch_bounds__(256)
cvt_kernel(const float* __restrict__ a0, const float* __restrict__ a1,
           const float* __restrict__ a2)
{
    const int z = blockIdx.y;
    const float* A = (z == 0) ? a0 : ((z == 1) ? a1 : a2);
    __nv_bfloat16* D = g_fbuf[z];
    const int n = NROWS * DIM / 4;
    for (int i = blockIdx.x * blockDim.x + threadIdx.x; i < n;
         i += gridDim.x * blockDim.x) {
        float4 v = *(const float4*)(A + (size_t)i * 4);
        uint2 h;
        cvt_h(v, h);
        *(uint2*)(D + (size_t)i * 4) = h;
    }
}

// ---- fragment helpers (warp tile 64x32); regb = operand region size ----
__device__ __forceinline__ void load_frags(uint32_t u, uint32_t regb, int kk,
                                           int wm, int wn, int g, int tr,
                                           uint32_t ah[4][4], uint32_t bh[2][4]) {
    const int rowB = kk + ((g & 1) ? 8 : 0) + tr;
#pragma unroll
    for (int nb = 0; nb < 2; nb++)
        ldsm4t(bh[nb], swz256(u + regb, rowB, (wn >> 3) + nb * 2 + (g >> 1)));
    const int rowA = kk + ((g & 2) ? 8 : 0) + tr;
#pragma unroll
    for (int mi = 0; mi < 4; mi++)
        ldsm4t(ah[mi], swz256(u, rowA, (wm >> 3) + mi * 2 + (g & 1)));
}

__device__ __forceinline__ void mma_step(float acc[4][4][4],
                                         uint32_t ah[4][4], uint32_t bh[2][4]) {
#pragma unroll
    for (int mi = 0; mi < 4; mi++)
#pragma unroll
        for (int nj = 0; nj < 4; nj++)
            mma16816(acc[mi][nj], ah[mi],
                     bh[nj >> 1][(nj & 1) * 2], bh[nj >> 1][(nj & 1) * 2 + 1]);
}

// ====== Gram kernel (R13-proven, unchanged): cp.async bf16, fp32 partials ===
__global__ void __launch_bounds__(256, 1)
gram_cp_kernel()
{
    extern __shared__ __align__(16) char dynsmem[];

    const int z  = blockIdx.z;
    const int ky = blockIdx.y;
    const __nv_bfloat16* Ab = g_fbuf[z];
    float* C = g_part[ky][z];

    int t = blockIdx.x, bi = 0;
    while (t >= 8 - bi) { t -= 8 - bi; bi++; }
    const int bj = bi + t;
    const int i0 = bi * 128, j0 = bj * 128;

    const int tid = threadIdx.x;
    const int w = tid >> 5, l = tid & 31;
    const int wm = (w >> 2) * 64;
    const int wn = (w & 3) * 32;
    const int tr = l & 7, g = l >> 3;
    const int row = tid >> 3;
    const int cb  = (tid & 7) * 2;

    const uint32_t sb = smem_u32(dynsmem);

    float acc[4][4][4];
#pragma unroll
    for (int mi = 0; mi < 4; mi++)
#pragma unroll
        for (int nj = 0; nj < 4; nj++)
#pragma unroll
            for (int q = 0; q < 4; q++) acc[mi][nj][q] = 0.0f;

    const __nv_bfloat16* baseI = Ab + i0;
    const __nv_bfloat16* baseJ = Ab + j0;
    const int kbase = ky * (NROWS / KSPLIT);

    const int S = (NROWS / KSPLIT) / GKC;   // 64 stages

    auto issue_stage = [&](int s) {
        const uint32_t bufb = sb + (uint32_t)(s & (GNSTG - 1)) * GSTAGEB;
        const size_t krow = (size_t)(kbase + s * GKC + row) * DIM;
#pragma unroll
        for (int cc = 0; cc < 2; cc++) {
            const int ch = cb + cc;
            const uint32_t off = (uint32_t)(row * 256) + ((ch ^ (row & 7)) << 4);
            CP_ASYNC16(bufb + off,         baseI + krow + ch * 8);
            CP_ASYNC16(bufb + GREGB + off, baseJ + krow + ch * 8);
        }
    };

    issue_stage(0); CP_COMMIT();
    issue_stage(1); CP_COMMIT();
    issue_stage(2); CP_COMMIT();

    for (int s = 0; s < S; s++) {
        CP_WAIT2();
        __syncthreads();
        if (s + 3 < S) issue_stage(s + 3);
        CP_COMMIT();
        const uint32_t u = sb + (uint32_t)(s & (GNSTG - 1)) * GSTAGEB;
        uint32_t ah[2][4][4], bh[2][2][4];
        load_frags(u, GREGB, 0, wm, wn, g, tr, ah[0], bh[0]);
#pragma unroll
        for (int kk = 0; kk < GKC; kk += 16) {
            const int cu = (kk >> 4) & 1;
            if (kk + 16 < GKC)
                load_frags(u, GREGB, kk + 16, wm, wn, g, tr, ah[cu ^ 1], bh[cu ^ 1]);
            mma_step(acc, ah[cu], bh[cu]);
        }
    }

    // epilogue: fp32 partial store + mirror (R13-proven)
    const int r  = l >> 2;
    const int c2 = 2 * (l & 3);
#pragma unroll
    for (int mi = 0; mi < 4; mi++) {
#pragma unroll
        for (int nj = 0; nj < 4; nj++) {
            float* a = acc[mi][nj];
            const int gr = i0 + wm + mi * 16 + r;
            const int gc = j0 + wn + nj * 8 + c2;
            *(float2*)&C[(size_t)gr * DIM + gc]       = make_float2(a[0], a[1]);
            *(float2*)&C[(size_t)(gr + 8) * DIM + gc] = make_float2(a[2], a[3]);
            if (bi != bj) {
                C[(size_t)gc * DIM + gr]           = a[0];
                C[(size_t)(gc + 1) * DIM + gr]     = a[1];
                C[(size_t)gc * DIM + gr + 8]       = a[2];
                C[(size_t)(gc + 1) * DIM + gr + 8] = a[3];
            }
        }
    }
}

// ============ sum 4 fp32 partial planes -> bf16 G in hbuf[0] ============
__global__ void __launch_bounds__(256)
add32_kernel()
{
    const int z = blockIdx.y;
    const float4* p0 = reinterpret_cast<const float4*>(g_part[0][z]);
    const float4* p1 = reinterpret_cast<const float4*>(g_part[1][z]);
    const float4* p2 = reinterpret_cast<const float4*>(g_part[2][z]);
    const float4* p3 = reinterpret_cast<const float4*>(g_part[3][z]);
    uint2* d = reinterpret_cast<uint2*>(g_hbuf[0][z]);
    const int n = DIM * DIM / 4;
    for (int i = blockIdx.x * blockDim.x + threadIdx.x; i < n;
         i += gridDim.x * blockDim.x) {
        float4 a = p0[i], b = p1[i], c = p2[i], e = p3[i];
        float4 v;
        v.x = (a.x + b.x) + (c.x + e.x);
        v.y = (a.y + b.y) + (c.y + e.y);
        v.z = (a.z + b.z) + (c.z + e.z);
        v.w = (a.w + b.w) + (c.w + e.w);
        uint2 h;
        cvt_h(v, h);
        d[i] = h;
    }
}

// ---- shared epilogue for squaring kernel ----
__device__ __forceinline__ void sq_epilogue(float acc[4][4][4], int bi, int bj,
                                            int i0, int j0, int wm, int wn,
                                            int tid, int w, int l, float s2,
                                            int do_write, double wfin,
                                            __nv_bfloat16* Cb, int z,
                                            float* sh_wsum)
{
    const float w2 = (bi == bj) ? 1.0f : 2.0f;
    float fr = 0.0f;
    const int r  = l >> 2;
    const int c2 = 2 * (l & 3);
#pragma unroll
    for (int mi = 0; mi < 4; mi++) {
#pragma unroll
        for (int nj = 0; nj < 4; nj++) {
            float* a = acc[mi][nj];
#pragma unroll
            for (int q = 0; q < 4; q++) {
                a[q] *= s2;
                fr = fmaf(w2 * a[q], a[q], fr);
            }
            if (do_write) {
                const int gr = i0 + wm + mi * 16 + r;
                const int gc = j0 + wn + nj * 8 + c2;
                __nv_bfloat162 h01 = __floats2bfloat162_rn(a[0], a[1]);
                __nv_bfloat162 h23 = __floats2bfloat162_rn(a[2], a[3]);
                *reinterpret_cast<__nv_bfloat162*>(&Cb[(size_t)gr * DIM + gc]) = h01;
                *reinterpret_cast<__nv_bfloat162*>(&Cb[(size_t)(gr + 8) * DIM + gc]) = h23;
                if (bi != bj) {
                    Cb[(size_t)gc * DIM + gr]           = h01.x;
                    Cb[(size_t)(gc + 1) * DIM + gr]     = h01.y;
                    Cb[(size_t)gc * DIM + gr + 8]       = h23.x;
                    Cb[(size_t)(gc + 1) * DIM + gr + 8] = h23.y;
                }
            }
        }
    }
#pragma unroll
    for (int o = 16; o > 0; o >>= 1)
        fr += __shfl_xor_sync(0xffffffffu, fr, o);
    if (l == 0) sh_wsum[w] = fr;
    __syncthreads();
    if (tid == 0) {
        double tot = 0.0;
        for (int i = 0; i < 8; i++) tot += (double)sh_wsum[i];
        atomicAdd(&g_frob[z], tot);
        __threadfence();
        int tk = atomicAdd(&g_ctr[z], 1);
        if (tk == NTILE - 1) {
            g_ctr[z] = 0;
            __threadfence();
            double c = sqrt(g_frob[z]);
            g_inv[z] = (float)(1.0 / c);
            g_logacc[z] += log2(c) * wfin;
            g_frob[z] = 0.0;
        }
    }
}

// ===== squaring: 4-stage cp.async pipeline, KC=64 (16 stages), bf16 chain ===
__global__ void __launch_bounds__(256, 1)
sq_cp_kernel(int src_sel, int dst_sel, int do_write, double wfin)
{
    extern __shared__ __align__(16) char dynsmem[];
    __shared__ float sh_wsum[8];

    const int z = blockIdx.z;
    const __nv_bfloat16* Ab = g_hbuf[src_sel][z];
    __nv_bfloat16* Cb = g_hbuf[dst_sel][z];

    int t = blockIdx.x, bi = 0;
    while (t >= 8 - bi) { t -= 8 - bi; bi++; }
    const int bj = bi + t;
    const int i0 = bi * 128, j0 = bj * 128;

    const int tid = threadIdx.x;
    const int w = tid >> 5, l = tid & 31;
    const int wm = (w >> 2) * 64;
    const int wn = (w & 3) * 32;
    const int tr = l & 7, g = l >> 3;
    const int row = tid >> 3;          // 0..31; also covers row+32
    const int cb  = (tid & 7) * 2;

    const float sv = g_inv[z];
    const float s2 = sv * sv;

    const uint32_t sb = smem_u32(dynsmem);

    float acc[4][4][4];
#pragma unroll
    for (int mi = 0; mi < 4; mi++)
#pragma unroll
        for (int nj = 0; nj < 4; nj++)
#pragma unroll
            for (int q = 0; q < 4; q++) acc[mi][nj][q] = 0.0f;

    const __nv_bfloat16* baseI = Ab + i0;
    const __nv_bfloat16* baseJ = Ab + j0;

    const int S = DIM / QKC;   // 16 stages

    auto issue_stage = [&](int s) {
        const uint32_t bufb = sb + (uint32_t)(s & (QNSTG - 1)) * QSTAGEB;
#pragma unroll
        for (int rr = 0; rr < 2; rr++) {
            const int rw = row + rr * 32;
            const size_t krow = (size_t)(s * QKC + rw) * DIM;
#pragma unroll
            for (int cc = 0; cc < 2; cc++) {
                const int ch = cb + cc;
                const uint32_t off = (uint32_t)(rw * 256) + ((ch ^ (rw & 7)) << 4);
                CP_ASYNC16(bufb + off,         baseI + krow + ch * 8);
                CP_ASYNC16(bufb + QREGB + off, baseJ + krow + ch * 8);
            }
        }
    };

    issue_stage(0); CP_COMMIT();
    issue_stage(1); CP_COMMIT();
    issue_stage(2); CP_COMMIT();

    for (int s = 0; s < S; s++) {
        CP_WAIT2();
        __syncthreads();
        if (s + 3 < S) issue_stage(s + 3);
        CP_COMMIT();
        const uint32_t u = sb + (uint32_t)(s & (QNSTG - 1)) * QSTAGEB;
        uint32_t ah[2][4][4], bh[2][2][4];
        load_frags(u, QREGB, 0, wm, wn, g, tr, ah[0], bh[0]);
#pragma unroll
        for (int kk = 0; kk < QKC; kk += 16) {
            const int cu = (kk >> 4) & 1;
            if (kk + 16 < QKC)
                load_frags(u, QREGB, kk + 16, wm, wn, g, tr, ah[cu ^ 1], bh[cu ^ 1]);
            mma_step(acc, ah[cu], bh[cu]);
        }
    }
    __syncthreads();

    sq_epilogue(acc, bi, bj, i0, j0, wm, wn, tid, w, l, s2, do_write, wfin,
                Cb, z, sh_wsum);
}

__global__ void out_kernel(float* __restrict__ out) {
    double l0 = exp2(g_logacc[0]);
    double l1 = exp2(g_logacc[1]);
    double l2 = exp2(g_logacc[2]);
    out[0] = (float)(l0 + 0.5 * (l1 + l2));
}

extern "C" void kernel_launch(void* const* d_in, const int* in_sizes, int n_in,
                              void* d_out, int out_size)
{
    const float* f1 = (const float*)d_in[0];
    const float* f2 = (const float*)d_in[1];
    const float* f3 = (const float*)d_in[2];
    (void)in_sizes; (void)n_in; (void)out_size;

    static int configured = 0;
    if (!configured) {
        cudaFuncSetAttribute(gram_cp_kernel,
                             cudaFuncAttributeMaxDynamicSharedMemorySize, GSMEMB);
        cudaFuncSetAttribute(sq_cp_kernel,
                             cudaFuncAttributeMaxDynamicSharedMemorySize, QSMEMB);
        configured = 1;
    }

    init_kernel<<<1, 4>>>();

    // F -> bf16
    cvt_kernel<<<dim3(192, 3), 256>>>(f1, f2, f3);

    // Gram: 4-way K-split into fp32 partial planes (R13-proven)
    gram_cp_kernel<<<dim3(NTILE, KSPLIT, 3), 256, GSMEMB>>>();

    // sum partials -> bf16 G in hbuf[0]
    add32_kernel<<<dim3(108, 3), 256>>>();

    // 9 squarings (k=1 has g_inv=1)
    int cur = 0;
    for (int k = 1; k <= M_SQ; k++) {
        int dst = 1 - cur;
        int dow = (k < M_SQ) ? 1 : 0;
        sq_cp_kernel<<<dim3(NTILE, 1, 3), 256, QSMEMB>>>(
            cur, dst, dow, exp2(-(double)k));
        cur = dst;
    }
    out_kernel<<<1, 1>>>((float*)d_out);
}

// round 17
// speedup vs baseline: 1.5918x; 1.0024x over previous
#include <cuda_runtime.h>
#include <cuda_bf16.h>
#include <math.h>
#include <stdint.h>

// ---------------------------------------------------------------------------
// BSPLoss: out = lam1 + 0.5*(lam2+lam3), lam_i = top eigenvalue of F_i^T F_i.
// Pipeline: F -> bf16 ; Gram via cp.async bf16 GEMM (4-way K-split, fp32
// partials, R13-proven) ; add32 sums partials -> bf16 G ; 9 Frobenius-
// normalized squarings via cp.async bf16 GEMM (KC=128, 8 stages, NSTG=3).
// log2(lam) = sum 2^-k log2(c_k).  All GEMMs mma.sync bf16, fp32 accum.
// ---------------------------------------------------------------------------

#define DIM    1024
#define NROWS  8192
#define M_SQ   9
#define NTILE  36
#define KSPLIT 4

// Gram kernel constants (R13-proven: KC=32, 4-stage, 64 KB)
#define GKC     32
#define GREGB   (GKC * 256)          // 8 KB
#define GSTAGEB (2 * GREGB)          // 16 KB
#define GNSTG   4
#define GSMEMB  (GNSTG * GSTAGEB)    // 64 KB

// Squaring kernel constants (KC=128, 3-stage, 192 KB)
#define QKC     128
#define QREGB   (QKC * 256)          // 32 KB
#define QSTAGEB (2 * QREGB)          // 64 KB
#define QNSTG   3
#define QSMEMB  (QNSTG * QSTAGEB)    // 192 KB

__device__ __align__(16) float          g_part[KSPLIT][3][DIM * DIM];
__device__ __align__(16) __nv_bfloat16  g_hbuf[2][3][DIM * DIM];
__device__ __align__(16) __nv_bfloat16  g_fbuf[3][NROWS * DIM];
__device__ double g_frob[3];
__device__ float  g_inv[3];
__device__ double g_logacc[3];
__device__ int    g_ctr[3];

__global__ void init_kernel() {
    int i = threadIdx.x;
    if (i < 3) { g_frob[i] = 0.0; g_inv[i] = 1.0f; g_logacc[i] = 0.0; g_ctr[i] = 0; }
}

__device__ __forceinline__ uint32_t smem_u32(const void* p) {
    uint32_t a;
    asm("{ .reg .u64 t; cvta.to.shared.u64 t, %1; cvt.u32.u64 %0, t; }"
        : "=r"(a) : "l"(p));
    return a;
}

__device__ __forceinline__ void ldsm4t(uint32_t* r, uint32_t addr) {
    asm volatile("ldmatrix.sync.aligned.m8n8.x4.trans.shared.b16 {%0,%1,%2,%3}, [%4];"
                 : "=r"(r[0]), "=r"(r[1]), "=r"(r[2]), "=r"(r[3]) : "r"(addr));
}

__device__ __forceinline__ void mma16816(float* c, const uint32_t* a,
                                         uint32_t b0, uint32_t b1) {
    asm volatile("mma.sync.aligned.m16n8k16.row.col.f32.bf16.bf16.f32 "
                 "{%0,%1,%2,%3}, {%4,%5,%6,%7}, {%8,%9}, {%0,%1,%2,%3};"
                 : "+f"(c[0]), "+f"(c[1]), "+f"(c[2]), "+f"(c[3])
                 : "r"(a[0]), "r"(a[1]), "r"(a[2]), "r"(a[3]), "r"(b0), "r"(b1));
}

__device__ __forceinline__ uint32_t swz256(uint32_t base, int row, int chunk) {
    return base + row * 256 + ((chunk ^ (row & 7)) << 4);
}

__device__ __forceinline__ void cvt_h(float4 v, uint2& hi) {
    __nv_bfloat162 h0 = __floats2bfloat162_rn(v.x, v.y);
    __nv_bfloat162 h1 = __floats2bfloat162_rn(v.z, v.w);
    hi.x = *(uint32_t*)&h0; hi.y = *(uint32_t*)&h1;
}

#define CP_ASYNC16(dst, src) \
    asm volatile("cp.async.ca.shared.global [%0], [%1], 16;" \
                 :: "r"(dst), "l"(src) : "memory")
#define CP_COMMIT() asm volatile("cp.async.commit_group;" ::: "memory")
#define CP_WAIT2()  asm volatile("cp.async.wait_group 2;" ::: "memory")
#define CP_WAIT1()  asm volatile("cp.async.wait_group 1;" ::: "memory")

// ============ fp32 -> bf16 conversion pre-pass ============
__global__ void __launch_bounds__(256)
cvt_kernel(const float* __restrict__ a0, const float* __restrict__ a1,
           const float* __restrict__ a2)
{
    const int z = blockIdx.y;
    const float* A = (z == 0) ? a0 : ((z == 1) ? a1 : a2);
    __nv_bfloat16* D = g_fbuf[z];
    const int n = NROWS * DIM / 4;
    for (int i = blockIdx.x * blockDim.x + threadIdx.x; i < n;
         i += gridDim.x * blockDim.x) {
        float4 v = *(const float4*)(A + (size_t)i * 4);
        uint2 h;
        cvt_h(v, h);
        *(uint2*)(D + (size_t)i * 4) = h;
    }
}

// ---- fragment helpers (warp tile 64x32); regb = operand region size ----
__device__ __forceinline__ void load_frags(uint32_t u, uint32_t regb, int kk,
                                           int wm, int wn, int g, int tr,
                                           uint32_t ah[4][4], uint32_t bh[2][4]) {
    const int rowB = kk + ((g & 1) ? 8 : 0) + tr;
#pragma unroll
    for (int nb = 0; nb < 2; nb++)
        ldsm4t(bh[nb], swz256(u + regb, rowB, (wn >> 3) + nb * 2 + (g >> 1)));
    const int rowA = kk + ((g & 2) ? 8 : 0) + tr;
#pragma unroll
    for (int mi = 0; mi < 4; mi++)
        ldsm4t(ah[mi], swz256(u, rowA, (wm >> 3) + mi * 2 + (g & 1)));
}

__device__ __forceinline__ void mma_step(float acc[4][4][4],
                                         uint32_t ah[4][4], uint32_t bh[2][4]) {
#pragma unroll
    for (int mi = 0; mi < 4; mi++)
#pragma unroll
        for (int nj = 0; nj < 4; nj++)
            mma16816(acc[mi][nj], ah[mi],
                     bh[nj >> 1][(nj & 1) * 2], bh[nj >> 1][(nj & 1) * 2 + 1]);
}

// ====== Gram kernel (R13-proven, unchanged): cp.async bf16, fp32 partials ===
__global__ void __launch_bounds__(256, 1)
gram_cp_kernel()
{
    extern __shared__ __align__(16) char dynsmem[];

    const int z  = blockIdx.z;
    const int ky = blockIdx.y;
    const __nv_bfloat16* Ab = g_fbuf[z];
    float* C = g_part[ky][z];

    int t = blockIdx.x, bi = 0;
    while (t >= 8 - bi) { t -= 8 - bi; bi++; }
    const int bj = bi + t;
    const int i0 = bi * 128, j0 = bj * 128;

    const int tid = threadIdx.x;
    const int w = tid >> 5, l = tid & 31;
    const int wm = (w >> 2) * 64;
    const int wn = (w & 3) * 32;
    const int tr = l & 7, g = l >> 3;
    const int row = tid >> 3;
    const int cb  = (tid & 7) * 2;

    const uint32_t sb = smem_u32(dynsmem);

    float acc[4][4][4];
#pragma unroll
    for (int mi = 0; mi < 4; mi++)
#pragma unroll
        for (int nj = 0; nj < 4; nj++)
#pragma unroll
            for (int q = 0; q < 4; q++) acc[mi][nj][q] = 0.0f;

    const __nv_bfloat16* baseI = Ab + i0;
    const __nv_bfloat16* baseJ = Ab + j0;
    const int kbase = ky * (NROWS / KSPLIT);

    const int S = (NROWS / KSPLIT) / GKC;   // 64 stages

    auto issue_stage = [&](int s) {
        const uint32_t bufb = sb + (uint32_t)(s & (GNSTG - 1)) * GSTAGEB;
        const size_t krow = (size_t)(kbase + s * GKC + row) * DIM;
#pragma unroll
        for (int cc = 0; cc < 2; cc++) {
            const int ch = cb + cc;
            const uint32_t off = (uint32_t)(row * 256) + ((ch ^ (row & 7)) << 4);
            CP_ASYNC16(bufb + off,         baseI + krow + ch * 8);
            CP_ASYNC16(bufb + GREGB + off, baseJ + krow + ch * 8);
        }
    };

    issue_stage(0); CP_COMMIT();
    issue_stage(1); CP_COMMIT();
    issue_stage(2); CP_COMMIT();

    for (int s = 0; s < S; s++) {
        CP_WAIT2();
        __syncthreads();
        if (s + 3 < S) issue_stage(s + 3);
        CP_COMMIT();
        const uint32_t u = sb + (uint32_t)(s & (GNSTG - 1)) * GSTAGEB;
        uint32_t ah[2][4][4], bh[2][2][4];
        load_frags(u, GREGB, 0, wm, wn, g, tr, ah[0], bh[0]);
#pragma unroll
        for (int kk = 0; kk < GKC; kk += 16) {
            const int cu = (kk >> 4) & 1;
            if (kk + 16 < GKC)
                load_frags(u, GREGB, kk + 16, wm, wn, g, tr, ah[cu ^ 1], bh[cu ^ 1]);
            mma_step(acc, ah[cu], bh[cu]);
        }
    }

    // epilogue: fp32 partial store + mirror (R13-proven)
    const int r  = l >> 2;
    const int c2 = 2 * (l & 3);
#pragma unroll
    for (int mi = 0; mi < 4; mi++) {
#pragma unroll
        for (int nj = 0; nj < 4; nj++) {
            float* a = acc[mi][nj];
            const int gr = i0 + wm + mi * 16 + r;
            const int gc = j0 + wn + nj * 8 + c2;
            *(float2*)&C[(size_t)gr * DIM + gc]       = make_float2(a[0], a[1]);
            *(float2*)&C[(size_t)(gr + 8) * DIM + gc] = make_float2(a[2], a[3]);
            if (bi != bj) {
                C[(size_t)gc * DIM + gr]           = a[0];
                C[(size_t)(gc + 1) * DIM + gr]     = a[1];
                C[(size_t)gc * DIM + gr + 8]       = a[2];
                C[(size_t)(gc + 1) * DIM + gr + 8] = a[3];
            }
        }
    }
}

// ============ sum 4 fp32 partial planes -> bf16 G in hbuf[0] ============
__global__ void __launch_bounds__(256)
add32_kernel()
{
    const int z = blockIdx.y;
    const float4* p0 = reinterpret_cast<const float4*>(g_part[0][z]);
    const float4* p1 = reinterpret_cast<const float4*>(g_part[1][z]);
    const float4* p2 = reinterpret_cast<const float4*>(g_part[2][z]);
    const float4* p3 = reinterpret_cast<const float4*>(g_part[3][z]);
    uint2* d = reinterpret_cast<uint2*>(g_hbuf[0][z]);
    const int n = DIM * DIM / 4;
    for (int i = blockIdx.x * blockDim.x + threadIdx.x; i < n;
         i += gridDim.x * blockDim.x) {
        float4 a = p0[i], b = p1[i], c = p2[i], e = p3[i];
        float4 v;
        v.x = (a.x + b.x) + (c.x + e.x);
        v.y = (a.y + b.y) + (c.y + e.y);
        v.z = (a.z + b.z) + (c.z + e.z);
        v.w = (a.w + b.w) + (c.w + e.w);
        uint2 h;
        cvt_h(v, h);
        d[i] = h;
    }
}

// ---- shared epilogue for squaring kernel ----
__device__ __forceinline__ void sq_epilogue(float acc[4][4][4], int bi, int bj,
                                            int i0, int j0, int wm, int wn,
                                            int tid, int w, int l, float s2,
                                            int do_write, double wfin,
                                            __nv_bfloat16* Cb, int z,
                                            float* sh_wsum)
{
    const float w2 = (bi == bj) ? 1.0f : 2.0f;
    float fr = 0.0f;
    const int r  = l >> 2;
    const int c2 = 2 * (l & 3);
#pragma unroll
    for (int mi = 0; mi < 4; mi++) {
#pragma unroll
        for (int nj = 0; nj < 4; nj++) {
            float* a = acc[mi][nj];
#pragma unroll
            for (int q = 0; q < 4; q++) {
                a[q] *= s2;
                fr = fmaf(w2 * a[q], a[q], fr);
            }
            if (do_write) {
                const int gr = i0 + wm + mi * 16 + r;
                const int gc = j0 + wn + nj * 8 + c2;
                __nv_bfloat162 h01 = __floats2bfloat162_rn(a[0], a[1]);
                __nv_bfloat162 h23 = __floats2bfloat162_rn(a[2], a[3]);
                *reinterpret_cast<__nv_bfloat162*>(&Cb[(size_t)gr * DIM + gc]) = h01;
                *reinterpret_cast<__nv_bfloat162*>(&Cb[(size_t)(gr + 8) * DIM + gc]) = h23;
                if (bi != bj) {
                    Cb[(size_t)gc * DIM + gr]           = h01.x;
                    Cb[(size_t)(gc + 1) * DIM + gr]     = h01.y;
                    Cb[(size_t)gc * DIM + gr + 8]       = h23.x;
                    Cb[(size_t)(gc + 1) * DIM + gr + 8] = h23.y;
                }
            }
        }
    }
#pragma unroll
    for (int o = 16; o > 0; o >>= 1)
        fr += __shfl_xor_sync(0xffffffffu, fr, o);
    if (l == 0) sh_wsum[w] = fr;
    __syncthreads();
    if (tid == 0) {
        double tot = 0.0;
        for (int i = 0; i < 8; i++) tot += (double)sh_wsum[i];
        atomicAdd(&g_frob[z], tot);
        __threadfence();
        int tk = atomicAdd(&g_ctr[z], 1);
        if (tk == NTILE - 1) {
            g_ctr[z] = 0;
            __threadfence();
            double c = sqrt(g_frob[z]);
            g_inv[z] = (float)(1.0 / c);
            g_logacc[z] += log2(c) * wfin;
            g_frob[z] = 0.0;
        }
    }
}

// ===== squaring: 3-stage cp.async pipeline, KC=128 (8 stages), bf16 chain ===
__global__ void __launch_bounds__(256, 1)
sq_cp_kernel(int src_sel, int dst_sel, int do_write, double wfin)
{
    extern __shared__ __align__(16) char dynsmem[];
    __shared__ float sh_wsum[8];

    const int z = blockIdx.z;
    const __nv_bfloat16* Ab = g_hbuf[src_sel][z];
    __nv_bfloat16* Cb = g_hbuf[dst_sel][z];

    int t = blockIdx.x, bi = 0;
    while (t >= 8 - bi) { t -= 8 - bi; bi++; }
    const int bj = bi + t;
    const int i0 = bi * 128, j0 = bj * 128;

    const int tid = threadIdx.x;
    const int w = tid >> 5, l = tid & 31;
    const int wm = (w >> 2) * 64;
    const int wn = (w & 3) * 32;
    const int tr = l & 7, g = l >> 3;
    const int row = tid >> 3;          // 0..31; rr loop covers +32,+64,+96
    const int cb  = (tid & 7) * 2;

    const float sv = g_inv[z];
    const float s2 = sv * sv;

    const uint32_t sb = smem_u32(dynsmem);

    float acc[4][4][4];
#pragma unroll
    for (int mi = 0; mi < 4; mi++)
#pragma unroll
        for (int nj = 0; nj < 4; nj++)
#pragma unroll
            for (int q = 0; q < 4; q++) acc[mi][nj][q] = 0.0f;

    const __nv_bfloat16* baseI = Ab + i0;
    const __nv_bfloat16* baseJ = Ab + j0;

    const int S = DIM / QKC;   // 8 stages

    auto issue_stage = [&](int s) {
        const uint32_t bufb = sb + (uint32_t)(s % QNSTG) * QSTAGEB;
#pragma unroll
        for (int rr = 0; rr < 4; rr++) {
            const int rw = row + rr * 32;
            const size_t krow = (size_t)(s * QKC + rw) * DIM;
#pragma unroll
            for (int cc = 0; cc < 2; cc++) {
                const int ch = cb + cc;
                const uint32_t off = (uint32_t)(rw * 256) + ((ch ^ (rw & 7)) << 4);
                CP_ASYNC16(bufb + off,         baseI + krow + ch * 8);
                CP_ASYNC16(bufb + QREGB + off, baseJ + krow + ch * 8);
            }
        }
    };

    issue_stage(0); CP_COMMIT();
    issue_stage(1); CP_COMMIT();

    for (int s = 0; s < S; s++) {
        CP_WAIT1();
        __syncthreads();
        if (s + 2 < S) issue_stage(s + 2);
        CP_COMMIT();
        const uint32_t u = sb + (uint32_t)(s % QNSTG) * QSTAGEB;
        uint32_t ah[2][4][4], bh[2][2][4];
        load_frags(u, QREGB, 0, wm, wn, g, tr, ah[0], bh[0]);
#pragma unroll
        for (int kk = 0; kk < QKC; kk += 16) {
            const int cu = (kk >> 4) & 1;
            if (kk + 16 < QKC)
                load_frags(u, QREGB, kk + 16, wm, wn, g, tr, ah[cu ^ 1], bh[cu ^ 1]);
            mma_step(acc, ah[cu], bh[cu]);
        }
    }
    __syncthreads();

    sq_epilogue(acc, bi, bj, i0, j0, wm, wn, tid, w, l, s2, do_write, wfin,
                Cb, z, sh_wsum);
}

__global__ void out_kernel(float* __restrict__ out) {
    double l0 = exp2(g_logacc[0]);
    double l1 = exp2(g_logacc[1]);
    double l2 = exp2(g_logacc[2]);
    out[0] = (float)(l0 + 0.5 * (l1 + l2));
}

extern "C" void kernel_launch(void* const* d_in, const int* in_sizes, int n_in,
                              void* d_out, int out_size)
{
    const float* f1 = (const float*)d_in[0];
    const float* f2 = (const float*)d_in[1];
    const float* f3 = (const float*)d_in[2];
    (void)in_sizes; (void)n_in; (void)out_size;

    static int configured = 0;
    if (!configured) {
        cudaFuncSetAttribute(gram_cp_kernel,
                             cudaFuncAttributeMaxDynamicSharedMemorySize, GSMEMB);
        cudaFuncSetAttribute(sq_cp_kernel,
                             cudaFuncAttributeMaxDynamicSharedMemorySize, QSMEMB);
        configured = 1;
    }

    init_kernel<<<1, 4>>>();

    // F -> bf16
    cvt_kernel<<<dim3(192, 3), 256>>>(f1, f2, f3);

    // Gram: 4-way K-split into fp32 partial planes (R13-proven)
    gram_cp_kernel<<<dim3(NTILE, KSPLIT, 3), 256, GSMEMB>>>();

    // sum partials -> bf16 G in hbuf[0]
    add32_kernel<<<dim3(108, 3), 256>>>();

    // 9 squarings (k=1 has g_inv=1)
    int cur = 0;
    for (int k = 1; k <= M_SQ; k++) {
        int dst = 1 - cur;
        int dow = (k < M_SQ) ? 1 : 0;
        sq_cp_kernel<<<dim3(NTILE, 1, 3), 256, QSMEMB>>>(
            cur, dst, dow, exp2(-(double)k));
        cur = dst;
    }
    out_kernel<<<1, 1>>>((float*)d_out);
}